// round 14
// baseline (speedup 1.0000x reference)
#include <cuda_runtime.h>
#include <cuda_bf16.h>
#include <math.h>
#include <stdint.h>

// Problem constants
#define NB 8
#define NC 256
#define NHW 1024
#define NROW 8192              // NB*NHW
#define INV_T 10.0f            // 1/TEMPERATURE
#define POS_COUNT 8388608.0    // 8192*1024

#define GEMM_GRID 296          // 2 CTAs/SM * 148 SMs, single balanced wave
#define NJOBS 8192             // 64 rowblocks * 128 col-tiles (64 cols each)

// ---------------- device scratch (no allocation allowed) ----------------
__device__ __align__(256) __nv_bfloat16 g_Rn[NROW * NC];   // normalized rgb (bf16)
__device__ __align__(256) __nv_bfloat16 g_Xn[NROW * NC];   // normalized x   (bf16)
__device__ float  g_Xsum[8 * NC];           // per-batch column sums of normalized x
__device__ float  g_Rsum[8 * NC];           // per-batch column sums of normalized rgb
__device__ float  g_rowsum[NROW];           // sum_j exp(sim_ij)
__device__ double g_acc;                    // global loss accumulator
__device__ unsigned g_done;                 // k_final completion counter

__device__ __forceinline__ float ex2f(float x) {
    float r; asm("ex2.approx.f32 %0, %1;" : "=f"(r) : "f"(x)); return r;
}
__device__ __forceinline__ float lg2f(float x) {
    float r; asm("lg2.approx.f32 %0, %1;" : "=f"(r) : "f"(x)); return r;
}

// ---------------- init: 1 block, tiny ------------------------------------
__global__ void k_init() {
    int tid = threadIdx.x;
    #pragma unroll
    for (int i = 0; i < 8; ++i) {
        g_Xsum[tid + i * 256] = 0.0f;
        g_Rsum[tid + i * 256] = 0.0f;
    }
    if (tid == 0) { g_acc = 0.0; g_done = 0u; }
}

// ---------------- normalize (B,C,H,W) -> rows of 256, bf16 --------------
// grid 512: blocks [0,256) process rgb, [256,512) process x.
// Accumulates per-batch sums (Rsum / Xsum), zeroes g_rowsum, and writes the
// bf16 output via a staged smem tile so stores are 512B/warp coalesced.
__global__ void __launch_bounds__(256) k_norm(const float* __restrict__ rgb,
                                              const float* __restrict__ x) {
    __shared__ float s[32][257];
    __shared__ float ps[8][32];
    __shared__ float invs[32];
    __shared__ __nv_bfloat16 h[32 * 256];   // staged bf16 output tile (16KB, contiguous)

    int tid = threadIdx.x;
    // each of 512 blocks zeroes 16 entries of g_rowsum (runs before k_gemm)
    if (tid < 16) g_rowsum[blockIdx.x * 16 + tid] = 0.0f;

    int isX = blockIdx.x >> 8;
    int bix = blockIdx.x & 255;
    int b   = bix >> 5;
    int p0  = (bix & 31) << 5;
    int pl  = tid & 31;
    int cg  = tid >> 5;

    const float* in = isX ? x : rgb;
    const float* base = in + (size_t)b * NC * NHW + p0;
    #pragma unroll
    for (int co = 0; co < 32; ++co) {
        int c = co * 8 + cg;
        s[pl][c] = base[(size_t)c * NHW + pl];
    }
    __syncthreads();

    float part = 0.0f;
    #pragma unroll
    for (int k = 0; k < 32; ++k) {
        float v = s[pl][cg * 32 + k];
        part = fmaf(v, v, part);
    }
    ps[cg][pl] = part;
    __syncthreads();

    if (tid < 32) {
        float ss = 0.0f;
        #pragma unroll
        for (int j = 0; j < 8; ++j) ss += ps[j][tid];
        invs[tid] = 1.0f / fmaxf(sqrtf(ss), 1e-12f);
    }
    __syncthreads();

    float* sacc = isX ? g_Xsum : g_Rsum;

    float acc = 0.0f;
    #pragma unroll
    for (int rl = 0; rl < 32; ++rl) {
        float v = s[rl][tid] * invs[rl];
        h[rl * 256 + tid] = __float2bfloat16(v);
        acc += v;                      // all 32 pixels in this block share batch b
    }
    atomicAdd(&sacc[b * NC + tid], acc);
    __syncthreads();

    // vectorized write: the 32x256 bf16 tile is one contiguous 16KB region
    {
        __nv_bfloat16* out = isX ? g_Xn : g_Rn;
        uint4* dst = (uint4*)(out + (size_t)(b * NHW + p0) * NC);
        const uint4* src = (const uint4*)h;
        #pragma unroll
        for (int k = 0; k < 4; ++k)
            dst[tid + k * 256] = src[tid + k * 256];
    }
}

// ---------------- helpers for the GEMM ----------------------------------
__device__ __forceinline__ void mma16816(float c[4], const uint32_t a[4],
                                         uint32_t b0, uint32_t b1) {
    asm volatile(
        "mma.sync.aligned.m16n8k16.row.col.f32.bf16.bf16.f32 "
        "{%0,%1,%2,%3}, {%4,%5,%6,%7}, {%8,%9}, {%0,%1,%2,%3};"
        : "+f"(c[0]), "+f"(c[1]), "+f"(c[2]), "+f"(c[3])
        : "r"(a[0]), "r"(a[1]), "r"(a[2]), "r"(a[3]), "r"(b0), "r"(b1));
}
__device__ __forceinline__ void ldsm4(uint32_t b[4], uint32_t addr) {
    asm volatile("ldmatrix.sync.aligned.m8n8.x4.shared.b16 {%0,%1,%2,%3}, [%4];"
                 : "=r"(b[0]), "=r"(b[1]), "=r"(b[2]), "=r"(b[3]) : "r"(addr));
}

#define BUFW (64u * 132u * 4u)   // one 64x256 bf16 stage, padded stride 132 words

// issue 64x256 bf16 tile load (32KB) via cp.async, one commit group
__device__ __forceinline__ void issue_job(uint32_t dst_base, int job, int w, int lane) {
    const __nv_bfloat16* src_base = g_Xn + (size_t)(job & 127) * 64 * NC;
    const char* src = (const char*)src_base + lane * 16;
    #pragma unroll
    for (int it = 0; it < 8; ++it) {
        int row = it * 8 + w;
        uint32_t dst = dst_base + (uint32_t)(row * 132 + lane * 4) * 4;
        asm volatile("cp.async.cg.shared.global [%0], [%1], 16;"
                     :: "r"(dst), "l"(src + (size_t)row * 512) : "memory");
    }
    asm volatile("cp.async.commit_group;" ::: "memory");
}

// ---------------- fused GEMM + exp row-sum (static persistent) ----------
// 296 CTAs, each a contiguous range of the 8192 (rowblock, col-tile) jobs.
// job j: rowblock = j>>7 (128 rows), col tile = (j&127)*64.
// 8 warps; warp owns 16 rows; A register-resident per rowblock.
// 3-stage cp.async pipeline, 1 sync/job; LDSM->HMMA software pipeline.
__global__ void __launch_bounds__(256, 2) k_gemm() {
    extern __shared__ uint32_t Xs[];   // 3 stages of 64*132 words

    int tid  = threadIdx.x;
    int w    = tid >> 5;
    int lane = tid & 31;
    int g    = lane >> 2;
    int tig  = lane & 3;

    int k0 = (int)(((long long)blockIdx.x * NJOBS) / GEMM_GRID);
    int k1 = (int)(((long long)(blockIdx.x + 1) * NJOBS) / GEMM_GRID);

    // ldmatrix per-lane offset (q=0, kc=0), in words
    int mi = lane >> 3, rr = lane & 7;
    int ldsm_off = (((mi >> 1) * 8) + rr) * 132 + (mi & 1) * 4;

    uint32_t sbase = (uint32_t)__cvta_generic_to_shared(Xs);
    const float S = 14.426950408889634f;   // log2(e)/0.1

    issue_job(sbase, k0, w, lane);
    if (k0 + 1 < k1) issue_job(sbase + BUFW, k0 + 1, w, lane);

    uint32_t a[16][4];        // A fragments, K=256, for current rowblock
    int cur_rb = -1;
    float rs0 = 0.0f, rs1 = 0.0f;

    #pragma unroll 1
    for (int j = k0; j < k1; ++j) {
        int st = j - k0;
        if (j + 1 < k1) { asm volatile("cp.async.wait_group 1;" ::: "memory"); }
        else            { asm volatile("cp.async.wait_group 0;" ::: "memory"); }
        __syncthreads();   // all warps done with job j-1; stage (st+2)%3 free; stage st%3 visible
        if (j + 2 < k1)
            issue_job(sbase + (uint32_t)((st + 2) % 3) * BUFW, j + 2, w, lane);

        // rowblock change: flush rowsums, reload A fragments
        int rbn = j >> 7;
        if (rbn != cur_rb) {
            if (cur_rb >= 0) {
                float r0 = rs0, r1 = rs1;
                r0 += __shfl_xor_sync(0xffffffffu, r0, 1);
                r0 += __shfl_xor_sync(0xffffffffu, r0, 2);
                r1 += __shfl_xor_sync(0xffffffffu, r1, 1);
                r1 += __shfl_xor_sync(0xffffffffu, r1, 2);
                if (tig == 0) {
                    int rg = cur_rb * 128 + w * 16 + g;
                    atomicAdd(&g_rowsum[rg], r0);
                    atomicAdd(&g_rowsum[rg + 8], r1);
                }
                rs0 = 0.0f; rs1 = 0.0f;
            }
            const __nv_bfloat16* Ra = g_Rn + (size_t)(rbn * 128 + w * 16 + g) * NC;
            const __nv_bfloat16* Rb = Ra + 8 * NC;
            #pragma unroll
            for (int kc = 0; kc < 16; ++kc) {
                a[kc][0] = *(const uint32_t*)(Ra + kc * 16 + 2 * tig);
                a[kc][1] = *(const uint32_t*)(Rb + kc * 16 + 2 * tig);
                a[kc][2] = *(const uint32_t*)(Ra + kc * 16 + 8 + 2 * tig);
                a[kc][3] = *(const uint32_t*)(Rb + kc * 16 + 8 + 2 * tig);
            }
            cur_rb = rbn;
        }

        uint32_t tile_base = sbase + (uint32_t)(st % 3) * BUFW + (uint32_t)ldsm_off * 4;

        #pragma unroll
        for (int half = 0; half < 2; ++half) {
            float c[4][4];
            #pragma unroll
            for (int n8 = 0; n8 < 4; ++n8) {
                c[n8][0] = 0.f; c[n8][1] = 0.f; c[n8][2] = 0.f; c[n8][3] = 0.f;
            }
            uint32_t ld_base = tile_base + (uint32_t)(half * 2 * 2112) * 4;

            // software pipeline: b fragments loaded one (kc,q) step ahead
            uint32_t bb[2][4];
            ldsm4(bb[0], ld_base);                 // (kc=0, q=0)
            #pragma unroll
            for (int i = 0; i < 32; ++i) {
                int kc = i >> 1, q = i & 1;
                int ni = i + 1;
                if (ni < 32) {
                    uint32_t nad = ld_base + (uint32_t)((ni & 1) * 2112 + (ni >> 1) * 8) * 4;
                    ldsm4(bb[ni & 1], nad);
                }
                uint32_t* bq = bb[q];
                mma16816(c[2 * q],     a[kc], bq[0], bq[1]);
                mma16816(c[2 * q + 1], a[kc], bq[2], bq[3]);
            }

            #pragma unroll
            for (int n8 = 0; n8 < 4; ++n8) {
                rs0 += ex2f(c[n8][0] * S) + ex2f(c[n8][1] * S);
                rs1 += ex2f(c[n8][2] * S) + ex2f(c[n8][3] * S);
            }
        }
    }

    // final flush
    if (cur_rb >= 0) {
        rs0 += __shfl_xor_sync(0xffffffffu, rs0, 1);
        rs0 += __shfl_xor_sync(0xffffffffu, rs0, 2);
        rs1 += __shfl_xor_sync(0xffffffffu, rs1, 1);
        rs1 += __shfl_xor_sync(0xffffffffu, rs1, 2);
        if (tig == 0) {
            int rg = cur_rb * 128 + w * 16 + g;
            atomicAdd(&g_rowsum[rg], rs0);
            atomicAdd(&g_rowsum[rg + 8], rs1);
        }
    }
}

// ---------------- final: sum 1024*ln(rowsum) - INV_T*dot(Rsum,Xsum) -----
// grid 32 x 256: one row per thread; block 0 also computes the positive dot.
__global__ void __launch_bounds__(256) k_final(float* __restrict__ out) {
    __shared__ float wsum[8];
    __shared__ float psum[8];
    int tid  = threadIdx.x;
    int lane = tid & 31;
    int w    = tid >> 5;
    int row  = blockIdx.x * 256 + tid;

    // issue positive-dot loads first (block 0) so they overlap the log chain
    float pd = 0.0f;
    if (blockIdx.x == 0) {
        #pragma unroll
        for (int b = 0; b < 8; ++b)
            pd = fmaf(g_Rsum[b * NC + tid], g_Xsum[b * NC + tid], pd);
    }

    float v = lg2f(g_rowsum[row]);      // sum log2, scale once at the end
    #pragma unroll
    for (int o = 16; o; o >>= 1) v += __shfl_xor_sync(0xffffffffu, v, o);
    if (lane == 0) wsum[w] = v;

    if (blockIdx.x == 0) {
        #pragma unroll
        for (int o = 16; o; o >>= 1) pd += __shfl_xor_sync(0xffffffffu, pd, o);
        if (lane == 0) psum[w] = pd;
    }
    __syncthreads();

    if (tid == 0) {
        float bs = 0.0f;
        #pragma unroll
        for (int j = 0; j < 8; ++j) bs += wsum[j];
        bs *= 1024.0f * 0.6931471805599453f;   // *ln(2)*1024
        if (blockIdx.x == 0) {
            float pp = 0.0f;
            #pragma unroll
            for (int j = 0; j < 8; ++j) pp += psum[j];
            bs -= pp * INV_T;
        }
        atomicAdd(&g_acc, (double)bs);
        __threadfence();
        unsigned t = atomicAdd(&g_done, 1u);
        if (t == gridDim.x - 1) {
            out[0] = (float)(g_acc / (POS_COUNT + 1e-8));
        }
    }
}

extern "C" void kernel_launch(void* const* d_in, const int* in_sizes, int n_in,
                              void* d_out, int out_size) {
    const float* rgb = (const float*)d_in[0];
    const float* x   = (const float*)d_in[1];
    float* out = (float*)d_out;
    (void)in_sizes; (void)n_in; (void)out_size;

    const int GEMM_SMEM = 3 * 64 * 132 * 4;   // 101376 bytes
    cudaFuncSetAttribute(k_gemm, cudaFuncAttributeMaxDynamicSharedMemorySize, GEMM_SMEM);

    k_init<<<1, 256>>>();
    k_norm<<<512, 256>>>(rgb, x);
    k_gemm<<<GEMM_GRID, 256, GEMM_SMEM>>>();
    k_final<<<32, 256>>>(out);
}

// round 15
// speedup vs baseline: 1.0006x; 1.0006x over previous
#include <cuda_runtime.h>
#include <cuda_bf16.h>
#include <math.h>
#include <stdint.h>

// Problem constants
#define NB 8
#define NC 256
#define NHW 1024
#define NROW 8192              // NB*NHW
#define INV_T 10.0f            // 1/TEMPERATURE
#define POS_COUNT 8388608.0    // 8192*1024

#define GEMM_GRID 296          // 2 CTAs/SM * 148 SMs, single balanced wave
#define NJOBS 8192             // 64 rowblocks * 128 col-tiles (64 cols each)

// ---------------- device scratch (no allocation allowed) ----------------
__device__ __align__(256) __nv_bfloat16 g_Rn[NROW * NC];   // normalized rgb (bf16)
__device__ __align__(256) __nv_bfloat16 g_Xn[NROW * NC];   // normalized x   (bf16)
__device__ float  g_Xsum[8 * NC];           // per-batch column sums of normalized x
__device__ float  g_Rsum[8 * NC];           // per-batch column sums of normalized rgb
__device__ float  g_rowsum[NROW];           // sum_j exp(sim_ij)
__device__ double g_acc;                    // global loss accumulator
__device__ unsigned g_done;                 // k_final completion counter

__device__ __forceinline__ float ex2f(float x) {
    float r; asm("ex2.approx.f32 %0, %1;" : "=f"(r) : "f"(x)); return r;
}
__device__ __forceinline__ float lg2f(float x) {
    float r; asm("lg2.approx.f32 %0, %1;" : "=f"(r) : "f"(x)); return r;
}

// ---------------- init: 1 block, tiny ------------------------------------
__global__ void k_init() {
    int tid = threadIdx.x;
    #pragma unroll
    for (int i = 0; i < 8; ++i) {
        g_Xsum[tid + i * 256] = 0.0f;
        g_Rsum[tid + i * 256] = 0.0f;
    }
    if (tid == 0) { g_acc = 0.0; g_done = 0u; }
}

// ---------------- normalize (B,C,H,W) -> rows of 256, bf16 --------------
// grid 512: blocks [0,256) process rgb, [256,512) process x.
// Also accumulates per-batch sums (Rsum / Xsum) and zeroes g_rowsum.
__global__ void __launch_bounds__(256) k_norm(const float* __restrict__ rgb,
                                              const float* __restrict__ x) {
    __shared__ float s[32][257];
    __shared__ float ps[8][32];
    __shared__ float invs[32];

    int tid = threadIdx.x;
    // each of 512 blocks zeroes 16 entries of g_rowsum (runs before k_gemm)
    if (tid < 16) g_rowsum[blockIdx.x * 16 + tid] = 0.0f;

    int isX = blockIdx.x >> 8;
    int bix = blockIdx.x & 255;
    int b   = bix >> 5;
    int p0  = (bix & 31) << 5;
    int pl  = tid & 31;
    int cg  = tid >> 5;

    const float* in = isX ? x : rgb;
    const float* base = in + (size_t)b * NC * NHW + p0;
    #pragma unroll
    for (int co = 0; co < 32; ++co) {
        int c = co * 8 + cg;
        s[pl][c] = base[(size_t)c * NHW + pl];
    }
    __syncthreads();

    float part = 0.0f;
    #pragma unroll
    for (int k = 0; k < 32; ++k) {
        float v = s[pl][cg * 32 + k];
        part = fmaf(v, v, part);
    }
    ps[cg][pl] = part;
    __syncthreads();

    if (tid < 32) {
        float ss = 0.0f;
        #pragma unroll
        for (int j = 0; j < 8; ++j) ss += ps[j][tid];
        invs[tid] = 1.0f / fmaxf(sqrtf(ss), 1e-12f);
    }
    __syncthreads();

    __nv_bfloat16* out = isX ? g_Xn : g_Rn;
    float* sacc = isX ? g_Xsum : g_Rsum;

    float acc = 0.0f;
    #pragma unroll
    for (int rl = 0; rl < 32; ++rl) {
        float v = s[rl][tid] * invs[rl];
        out[(size_t)(b * NHW + p0 + rl) * NC + tid] = __float2bfloat16(v);
        acc += v;                      // all 32 pixels in this block share batch b
    }
    atomicAdd(&sacc[b * NC + tid], acc);
}

// ---------------- helpers for the GEMM ----------------------------------
__device__ __forceinline__ void mma16816(float c[4], const uint32_t a[4],
                                         uint32_t b0, uint32_t b1) {
    asm volatile(
        "mma.sync.aligned.m16n8k16.row.col.f32.bf16.bf16.f32 "
        "{%0,%1,%2,%3}, {%4,%5,%6,%7}, {%8,%9}, {%0,%1,%2,%3};"
        : "+f"(c[0]), "+f"(c[1]), "+f"(c[2]), "+f"(c[3])
        : "r"(a[0]), "r"(a[1]), "r"(a[2]), "r"(a[3]), "r"(b0), "r"(b1));
}
__device__ __forceinline__ void ldsm4(uint32_t b[4], uint32_t addr) {
    asm volatile("ldmatrix.sync.aligned.m8n8.x4.shared.b16 {%0,%1,%2,%3}, [%4];"
                 : "=r"(b[0]), "=r"(b[1]), "=r"(b[2]), "=r"(b[3]) : "r"(addr));
}

#define BUFW (64u * 132u * 4u)   // one 64x256 bf16 stage, padded stride 132 words

// issue 64x256 bf16 tile load (32KB) via cp.async, one commit group
__device__ __forceinline__ void issue_job(uint32_t dst_base, int job, int w, int lane) {
    const __nv_bfloat16* src_base = g_Xn + (size_t)(job & 127) * 64 * NC;
    const char* src = (const char*)src_base + lane * 16;
    #pragma unroll
    for (int it = 0; it < 8; ++it) {
        int row = it * 8 + w;
        uint32_t dst = dst_base + (uint32_t)(row * 132 + lane * 4) * 4;
        asm volatile("cp.async.cg.shared.global [%0], [%1], 16;"
                     :: "r"(dst), "l"(src + (size_t)row * 512) : "memory");
    }
    asm volatile("cp.async.commit_group;" ::: "memory");
}

// ---------------- fused GEMM + exp row-sum (static persistent) ----------
// 296 CTAs, each a contiguous range of the 8192 (rowblock, col-tile) jobs.
// job j: rowblock = j>>7 (128 rows), col tile = (j&127)*64.
// 8 warps; warp owns 16 rows; A register-resident per rowblock.
// 3-stage cp.async pipeline, 1 sync/job; LDSM->HMMA software pipeline.
__global__ void __launch_bounds__(256, 2) k_gemm() {
    extern __shared__ uint32_t Xs[];   // 3 stages of 64*132 words

    int tid  = threadIdx.x;
    int w    = tid >> 5;
    int lane = tid & 31;
    int g    = lane >> 2;
    int tig  = lane & 3;

    int k0 = (int)(((long long)blockIdx.x * NJOBS) / GEMM_GRID);
    int k1 = (int)(((long long)(blockIdx.x + 1) * NJOBS) / GEMM_GRID);

    // ldmatrix per-lane offset (q=0, kc=0), in words
    int mi = lane >> 3, rr = lane & 7;
    int ldsm_off = (((mi >> 1) * 8) + rr) * 132 + (mi & 1) * 4;

    uint32_t sbase = (uint32_t)__cvta_generic_to_shared(Xs);
    const float S = 14.426950408889634f;   // log2(e)/0.1

    issue_job(sbase, k0, w, lane);
    if (k0 + 1 < k1) issue_job(sbase + BUFW, k0 + 1, w, lane);

    uint32_t a[16][4];        // A fragments, K=256, for current rowblock
    int cur_rb = -1;
    float rs0a = 0.0f, rs0b = 0.0f, rs1a = 0.0f, rs1b = 0.0f;

    #pragma unroll 1
    for (int j = k0; j < k1; ++j) {
        int st = j - k0;
        if (j + 1 < k1) { asm volatile("cp.async.wait_group 1;" ::: "memory"); }
        else            { asm volatile("cp.async.wait_group 0;" ::: "memory"); }
        __syncthreads();   // all warps done with job j-1; stage (st+2)%3 free; stage st%3 visible
        if (j + 2 < k1)
            issue_job(sbase + (uint32_t)((st + 2) % 3) * BUFW, j + 2, w, lane);

        // rowblock change: flush rowsums, reload A fragments
        int rbn = j >> 7;
        if (rbn != cur_rb) {
            if (cur_rb >= 0) {
                float r0 = rs0a + rs0b, r1 = rs1a + rs1b;
                r0 += __shfl_xor_sync(0xffffffffu, r0, 1);
                r0 += __shfl_xor_sync(0xffffffffu, r0, 2);
                r1 += __shfl_xor_sync(0xffffffffu, r1, 1);
                r1 += __shfl_xor_sync(0xffffffffu, r1, 2);
                if (tig == 0) {
                    int rg = cur_rb * 128 + w * 16 + g;
                    atomicAdd(&g_rowsum[rg], r0);
                    atomicAdd(&g_rowsum[rg + 8], r1);
                }
                rs0a = 0.0f; rs0b = 0.0f; rs1a = 0.0f; rs1b = 0.0f;
            }
            const __nv_bfloat16* Ra = g_Rn + (size_t)(rbn * 128 + w * 16 + g) * NC;
            const __nv_bfloat16* Rb = Ra + 8 * NC;
            #pragma unroll
            for (int kc = 0; kc < 16; ++kc) {
                a[kc][0] = *(const uint32_t*)(Ra + kc * 16 + 2 * tig);
                a[kc][1] = *(const uint32_t*)(Rb + kc * 16 + 2 * tig);
                a[kc][2] = *(const uint32_t*)(Ra + kc * 16 + 8 + 2 * tig);
                a[kc][3] = *(const uint32_t*)(Rb + kc * 16 + 8 + 2 * tig);
            }
            cur_rb = rbn;
        }

        uint32_t tile_base = sbase + (uint32_t)(st % 3) * BUFW + (uint32_t)ldsm_off * 4;

        #pragma unroll
        for (int half = 0; half < 2; ++half) {
            float c[4][4];
            #pragma unroll
            for (int n8 = 0; n8 < 4; ++n8) {
                c[n8][0] = 0.f; c[n8][1] = 0.f; c[n8][2] = 0.f; c[n8][3] = 0.f;
            }
            uint32_t ld_base = tile_base + (uint32_t)(half * 2 * 2112) * 4;

            // software pipeline: b fragments loaded one (kc,q) step ahead
            uint32_t bb[2][4];
            ldsm4(bb[0], ld_base);                 // (kc=0, q=0)
            #pragma unroll
            for (int i = 0; i < 32; ++i) {
                int kc = i >> 1, q = i & 1;
                int ni = i + 1;
                if (ni < 32) {
                    uint32_t nad = ld_base + (uint32_t)((ni & 1) * 2112 + (ni >> 1) * 8) * 4;
                    ldsm4(bb[ni & 1], nad);
                }
                uint32_t* bq = bb[q];
                mma16816(c[2 * q],     a[kc], bq[0], bq[1]);
                mma16816(c[2 * q + 1], a[kc], bq[2], bq[3]);
            }

            // dual accumulators halve the serial FADD chain behind the MUFUs
            #pragma unroll
            for (int n8 = 0; n8 < 4; n8 += 2) {
                rs0a += ex2f(c[n8][0] * S) + ex2f(c[n8][1] * S);
                rs1a += ex2f(c[n8][2] * S) + ex2f(c[n8][3] * S);
                rs0b += ex2f(c[n8 + 1][0] * S) + ex2f(c[n8 + 1][1] * S);
                rs1b += ex2f(c[n8 + 1][2] * S) + ex2f(c[n8 + 1][3] * S);
            }
        }
    }

    // final flush
    if (cur_rb >= 0) {
        float r0 = rs0a + rs0b, r1 = rs1a + rs1b;
        r0 += __shfl_xor_sync(0xffffffffu, r0, 1);
        r0 += __shfl_xor_sync(0xffffffffu, r0, 2);
        r1 += __shfl_xor_sync(0xffffffffu, r1, 1);
        r1 += __shfl_xor_sync(0xffffffffu, r1, 2);
        if (tig == 0) {
            int rg = cur_rb * 128 + w * 16 + g;
            atomicAdd(&g_rowsum[rg], r0);
            atomicAdd(&g_rowsum[rg + 8], r1);
        }
    }
}

// ---------------- final: sum 1024*ln(rowsum) - INV_T*dot(Rsum,Xsum) -----
// grid 32 x 256: one row per thread; block 0 also computes the positive dot.
__global__ void __launch_bounds__(256) k_final(float* __restrict__ out) {
    __shared__ float wsum[8];
    __shared__ float psum[8];
    int tid  = threadIdx.x;
    int lane = tid & 31;
    int w    = tid >> 5;
    int row  = blockIdx.x * 256 + tid;

    // issue positive-dot loads first (block 0) so they overlap the log chain
    float pd = 0.0f;
    if (blockIdx.x == 0) {
        #pragma unroll
        for (int b = 0; b < 8; ++b)
            pd = fmaf(g_Rsum[b * NC + tid], g_Xsum[b * NC + tid], pd);
    }

    float v = lg2f(g_rowsum[row]);      // sum log2, scale once at the end
    #pragma unroll
    for (int o = 16; o; o >>= 1) v += __shfl_xor_sync(0xffffffffu, v, o);
    if (lane == 0) wsum[w] = v;

    if (blockIdx.x == 0) {
        #pragma unroll
        for (int o = 16; o; o >>= 1) pd += __shfl_xor_sync(0xffffffffu, pd, o);
        if (lane == 0) psum[w] = pd;
    }
    __syncthreads();

    if (tid == 0) {
        float bs = 0.0f;
        #pragma unroll
        for (int j = 0; j < 8; ++j) bs += wsum[j];
        bs *= 1024.0f * 0.6931471805599453f;   // *ln(2)*1024
        if (blockIdx.x == 0) {
            float pp = 0.0f;
            #pragma unroll
            for (int j = 0; j < 8; ++j) pp += psum[j];
            bs -= pp * INV_T;
        }
        atomicAdd(&g_acc, (double)bs);
        __threadfence();
        unsigned t = atomicAdd(&g_done, 1u);
        if (t == gridDim.x - 1) {
            out[0] = (float)(g_acc / (POS_COUNT + 1e-8));
        }
    }
}

extern "C" void kernel_launch(void* const* d_in, const int* in_sizes, int n_in,
                              void* d_out, int out_size) {
    const float* rgb = (const float*)d_in[0];
    const float* x   = (const float*)d_in[1];
    float* out = (float*)d_out;
    (void)in_sizes; (void)n_in; (void)out_size;

    const int GEMM_SMEM = 3 * 64 * 132 * 4;   // 101376 bytes
    cudaFuncSetAttribute(k_gemm, cudaFuncAttributeMaxDynamicSharedMemorySize, GEMM_SMEM);

    k_init<<<1, 256>>>();
    k_norm<<<512, 256>>>(rgb, x);
    k_gemm<<<GEMM_GRID, 256, GEMM_SMEM>>>();
    k_final<<<32, 256>>>(out);
}

// round 16
// speedup vs baseline: 1.0197x; 1.0191x over previous
#include <cuda_runtime.h>
#include <cuda_bf16.h>
#include <math.h>
#include <stdint.h>

// Problem constants
#define NB 8
#define NC 256
#define NHW 1024
#define NROW 8192              // NB*NHW
#define INV_T 10.0f            // 1/TEMPERATURE
#define POS_COUNT 8388608.0    // 8192*1024

#define GEMM_GRID 296          // 2 CTAs/SM * 148 SMs, single balanced wave
#define NJOBS 8192             // 64 rowblocks * 128 col-tiles (64 cols each)

// ---------------- device scratch (no allocation allowed) ----------------
__device__ __align__(256) __nv_bfloat16 g_Rn[NROW * NC];   // normalized rgb (bf16)
__device__ __align__(256) __nv_bfloat16 g_Xn[NROW * NC];   // normalized x   (bf16)
__device__ float  g_Xsum[8 * NC];           // per-batch column sums of normalized x
__device__ float  g_Rsum[8 * NC];           // per-batch column sums of normalized rgb
__device__ float  g_rowsum[NROW];           // sum_j exp(sim_ij)
__device__ double g_acc;                    // global loss accumulator
__device__ unsigned g_done;                 // k_final completion counter

__device__ __forceinline__ float ex2f(float x) {
    float r; asm("ex2.approx.f32 %0, %1;" : "=f"(r) : "f"(x)); return r;
}
__device__ __forceinline__ float lg2f(float x) {
    float r; asm("lg2.approx.f32 %0, %1;" : "=f"(r) : "f"(x)); return r;
}

// ---------------- init: 1 block, tiny ------------------------------------
__global__ void k_init() {
    int tid = threadIdx.x;
    #pragma unroll
    for (int i = 0; i < 8; ++i) {
        g_Xsum[tid + i * 256] = 0.0f;
        g_Rsum[tid + i * 256] = 0.0f;
    }
    if (tid == 0) { g_acc = 0.0; g_done = 0u; }
}

// ---------------- normalize (B,C,H,W) -> rows of 256, bf16 --------------
// grid 512: blocks [0,256) process rgb, [256,512) process x.
// Also accumulates per-batch sums (Rsum / Xsum) and zeroes g_rowsum.
__global__ void __launch_bounds__(256) k_norm(const float* __restrict__ rgb,
                                              const float* __restrict__ x) {
    __shared__ float s[32][257];
    __shared__ float ps[8][32];
    __shared__ float invs[32];

    int tid = threadIdx.x;
    // each of 512 blocks zeroes 16 entries of g_rowsum (runs before k_gemm)
    if (tid < 16) g_rowsum[blockIdx.x * 16 + tid] = 0.0f;

    int isX = blockIdx.x >> 8;
    int bix = blockIdx.x & 255;
    int b   = bix >> 5;
    int p0  = (bix & 31) << 5;
    int pl  = tid & 31;
    int cg  = tid >> 5;

    const float* in = isX ? x : rgb;
    const float* base = in + (size_t)b * NC * NHW + p0;
    #pragma unroll
    for (int co = 0; co < 32; ++co) {
        int c = co * 8 + cg;
        s[pl][c] = base[(size_t)c * NHW + pl];
    }
    __syncthreads();

    float part = 0.0f;
    #pragma unroll
    for (int k = 0; k < 32; ++k) {
        float v = s[pl][cg * 32 + k];
        part = fmaf(v, v, part);
    }
    ps[cg][pl] = part;
    __syncthreads();

    if (tid < 32) {
        float ss = 0.0f;
        #pragma unroll
        for (int j = 0; j < 8; ++j) ss += ps[j][tid];
        invs[tid] = 1.0f / fmaxf(sqrtf(ss), 1e-12f);
    }
    __syncthreads();

    __nv_bfloat16* out = isX ? g_Xn : g_Rn;
    float* sacc = isX ? g_Xsum : g_Rsum;

    float acc = 0.0f;
    #pragma unroll
    for (int rl = 0; rl < 32; ++rl) {
        float v = s[rl][tid] * invs[rl];
        out[(size_t)(b * NHW + p0 + rl) * NC + tid] = __float2bfloat16(v);
        acc += v;                      // all 32 pixels in this block share batch b
    }
    atomicAdd(&sacc[b * NC + tid], acc);
}

// ---------------- helpers for the GEMM ----------------------------------
__device__ __forceinline__ void mma16816(float c[4], const uint32_t a[4],
                                         uint32_t b0, uint32_t b1) {
    asm volatile(
        "mma.sync.aligned.m16n8k16.row.col.f32.bf16.bf16.f32 "
        "{%0,%1,%2,%3}, {%4,%5,%6,%7}, {%8,%9}, {%0,%1,%2,%3};"
        : "+f"(c[0]), "+f"(c[1]), "+f"(c[2]), "+f"(c[3])
        : "r"(a[0]), "r"(a[1]), "r"(a[2]), "r"(a[3]), "r"(b0), "r"(b1));
}
__device__ __forceinline__ void ldsm4(uint32_t b[4], uint32_t addr) {
    asm volatile("ldmatrix.sync.aligned.m8n8.x4.shared.b16 {%0,%1,%2,%3}, [%4];"
                 : "=r"(b[0]), "=r"(b[1]), "=r"(b[2]), "=r"(b[3]) : "r"(addr));
}

#define BUFW (64u * 132u * 4u)   // one 64x256 bf16 stage, padded stride 132 words

// issue 64x256 bf16 tile load (32KB) via cp.async, one commit group
__device__ __forceinline__ void issue_job(uint32_t dst_base, int job, int w, int lane) {
    const __nv_bfloat16* src_base = g_Xn + (size_t)(job & 127) * 64 * NC;
    const char* src = (const char*)src_base + lane * 16;
    #pragma unroll
    for (int it = 0; it < 8; ++it) {
        int row = it * 8 + w;
        uint32_t dst = dst_base + (uint32_t)(row * 132 + lane * 4) * 4;
        asm volatile("cp.async.cg.shared.global [%0], [%1], 16;"
                     :: "r"(dst), "l"(src + (size_t)row * 512) : "memory");
    }
    asm volatile("cp.async.commit_group;" ::: "memory");
}

// ---------------- fused GEMM + exp row-sum (static persistent) ----------
// 296 CTAs, each a contiguous range of the 8192 (rowblock, col-tile) jobs.
// job j: rowblock = j>>7 (128 rows), col tile = (j&127)*64.
// 8 warps; warp owns 16 rows; A register-resident per rowblock.
// 3-stage cp.async pipeline, 1 sync/job; LDSM->HMMA software pipeline.
__global__ void __launch_bounds__(256, 2) k_gemm() {
    extern __shared__ uint32_t Xs[];   // 3 stages of 64*132 words

    int tid  = threadIdx.x;
    int w    = tid >> 5;
    int lane = tid & 31;
    int g    = lane >> 2;
    int tig  = lane & 3;

    int k0 = (int)(((long long)blockIdx.x * NJOBS) / GEMM_GRID);
    int k1 = (int)(((long long)(blockIdx.x + 1) * NJOBS) / GEMM_GRID);

    // ldmatrix per-lane offset (q=0, kc=0), in words
    int mi = lane >> 3, rr = lane & 7;
    int ldsm_off = (((mi >> 1) * 8) + rr) * 132 + (mi & 1) * 4;

    uint32_t sbase = (uint32_t)__cvta_generic_to_shared(Xs);
    const float S = 14.426950408889634f;   // log2(e)/0.1

    issue_job(sbase, k0, w, lane);
    if (k0 + 1 < k1) issue_job(sbase + BUFW, k0 + 1, w, lane);

    uint32_t a[16][4];        // A fragments, K=256, for current rowblock
    int cur_rb = -1;
    float rs0 = 0.0f, rs1 = 0.0f;

    #pragma unroll 1
    for (int j = k0; j < k1; ++j) {
        int st = j - k0;
        if (j + 1 < k1) { asm volatile("cp.async.wait_group 1;" ::: "memory"); }
        else            { asm volatile("cp.async.wait_group 0;" ::: "memory"); }
        __syncthreads();   // all warps done with job j-1; stage (st+2)%3 free; stage st%3 visible
        if (j + 2 < k1)
            issue_job(sbase + (uint32_t)((st + 2) % 3) * BUFW, j + 2, w, lane);

        // rowblock change: flush rowsums, reload A fragments
        int rbn = j >> 7;
        if (rbn != cur_rb) {
            if (cur_rb >= 0) {
                float r0 = rs0, r1 = rs1;
                r0 += __shfl_xor_sync(0xffffffffu, r0, 1);
                r0 += __shfl_xor_sync(0xffffffffu, r0, 2);
                r1 += __shfl_xor_sync(0xffffffffu, r1, 1);
                r1 += __shfl_xor_sync(0xffffffffu, r1, 2);
                if (tig == 0) {
                    int rg = cur_rb * 128 + w * 16 + g;
                    atomicAdd(&g_rowsum[rg], r0);
                    atomicAdd(&g_rowsum[rg + 8], r1);
                }
                rs0 = 0.0f; rs1 = 0.0f;
            }
            const __nv_bfloat16* Ra = g_Rn + (size_t)(rbn * 128 + w * 16 + g) * NC;
            const __nv_bfloat16* Rb = Ra + 8 * NC;
            #pragma unroll
            for (int kc = 0; kc < 16; ++kc) {
                a[kc][0] = *(const uint32_t*)(Ra + kc * 16 + 2 * tig);
                a[kc][1] = *(const uint32_t*)(Rb + kc * 16 + 2 * tig);
                a[kc][2] = *(const uint32_t*)(Ra + kc * 16 + 8 + 2 * tig);
                a[kc][3] = *(const uint32_t*)(Rb + kc * 16 + 8 + 2 * tig);
            }
            cur_rb = rbn;
        }

        uint32_t tile_base = sbase + (uint32_t)(st % 3) * BUFW + (uint32_t)ldsm_off * 4;

        #pragma unroll
        for (int half = 0; half < 2; ++half) {
            float c[4][4];
            #pragma unroll
            for (int n8 = 0; n8 < 4; ++n8) {
                c[n8][0] = 0.f; c[n8][1] = 0.f; c[n8][2] = 0.f; c[n8][3] = 0.f;
            }
            uint32_t ld_base = tile_base + (uint32_t)(half * 2 * 2112) * 4;

            // software pipeline: b fragments loaded one (kc,q) step ahead
            uint32_t bb[2][4];
            ldsm4(bb[0], ld_base);                 // (kc=0, q=0)
            #pragma unroll
            for (int i = 0; i < 32; ++i) {
                int kc = i >> 1, q = i & 1;
                int ni = i + 1;
                if (ni < 32) {
                    uint32_t nad = ld_base + (uint32_t)((ni & 1) * 2112 + (ni >> 1) * 8) * 4;
                    ldsm4(bb[ni & 1], nad);
                }
                uint32_t* bq = bb[q];
                mma16816(c[2 * q],     a[kc], bq[0], bq[1]);
                mma16816(c[2 * q + 1], a[kc], bq[2], bq[3]);
            }

            #pragma unroll
            for (int n8 = 0; n8 < 4; ++n8) {
                rs0 += ex2f(c[n8][0] * S) + ex2f(c[n8][1] * S);
                rs1 += ex2f(c[n8][2] * S) + ex2f(c[n8][3] * S);
            }
        }
    }

    // final flush
    if (cur_rb >= 0) {
        rs0 += __shfl_xor_sync(0xffffffffu, rs0, 1);
        rs0 += __shfl_xor_sync(0xffffffffu, rs0, 2);
        rs1 += __shfl_xor_sync(0xffffffffu, rs1, 1);
        rs1 += __shfl_xor_sync(0xffffffffu, rs1, 2);
        if (tig == 0) {
            int rg = cur_rb * 128 + w * 16 + g;
            atomicAdd(&g_rowsum[rg], rs0);
            atomicAdd(&g_rowsum[rg + 8], rs1);
        }
    }
}

// ---------------- final: sum 1024*ln(rowsum) - INV_T*dot(Rsum,Xsum) -----
// grid 32 x 256: one row per thread; block 0 also computes the positive dot.
__global__ void __launch_bounds__(256) k_final(float* __restrict__ out) {
    __shared__ float wsum[8];
    __shared__ float psum[8];
    int tid  = threadIdx.x;
    int lane = tid & 31;
    int w    = tid >> 5;
    int row  = blockIdx.x * 256 + tid;

    // issue positive-dot loads first (block 0) so they overlap the log chain
    float pd = 0.0f;
    if (blockIdx.x == 0) {
        #pragma unroll
        for (int b = 0; b < 8; ++b)
            pd = fmaf(g_Rsum[b * NC + tid], g_Xsum[b * NC + tid], pd);
    }

    float v = lg2f(g_rowsum[row]);      // sum log2, scale once at the end
    #pragma unroll
    for (int o = 16; o; o >>= 1) v += __shfl_xor_sync(0xffffffffu, v, o);
    if (lane == 0) wsum[w] = v;

    if (blockIdx.x == 0) {
        #pragma unroll
        for (int o = 16; o; o >>= 1) pd += __shfl_xor_sync(0xffffffffu, pd, o);
        if (lane == 0) psum[w] = pd;
    }
    __syncthreads();

    if (tid == 0) {
        float bs = 0.0f;
        #pragma unroll
        for (int j = 0; j < 8; ++j) bs += wsum[j];
        bs *= 1024.0f * 0.6931471805599453f;   // *ln(2)*1024
        if (blockIdx.x == 0) {
            float pp = 0.0f;
            #pragma unroll
            for (int j = 0; j < 8; ++j) pp += psum[j];
            bs -= pp * INV_T;
        }
        atomicAdd(&g_acc, (double)bs);
        __threadfence();
        unsigned t = atomicAdd(&g_done, 1u);
        if (t == gridDim.x - 1) {
            out[0] = (float)(g_acc / (POS_COUNT + 1e-8));
        }
    }
}

extern "C" void kernel_launch(void* const* d_in, const int* in_sizes, int n_in,
                              void* d_out, int out_size) {
    const float* rgb = (const float*)d_in[0];
    const float* x   = (const float*)d_in[1];
    float* out = (float*)d_out;
    (void)in_sizes; (void)n_in; (void)out_size;

    const int GEMM_SMEM = 3 * 64 * 132 * 4;   // 101376 bytes
    cudaFuncSetAttribute(k_gemm, cudaFuncAttributeMaxDynamicSharedMemorySize, GEMM_SMEM);

    k_init<<<1, 256>>>();
    k_norm<<<512, 256>>>(rgb, x);
    k_gemm<<<GEMM_GRID, 256, GEMM_SMEM>>>();
    k_final<<<32, 256>>>(out);
}